// round 13
// baseline (speedup 1.0000x reference)
#include <cuda_runtime.h>
#include <math.h>

// Problem constants
constexpr int kB = 256, kN = 1152, kD = 8, kO = 10, kE = 16;
constexpr int kOE = kO * kE;  // 160

// Tiling: block owns 4 n and 32 batches, in 4 chunks of 8. 4 CTAs/SM.
constexpr int kNL   = 4;
constexpr int kTH   = 160;        // tid = nl(b0-1) + eg(b2-3)*4 + o(b4+)*16
constexpr int kGX   = kN / kNL;   // 288
constexpr int kGY   = 8;
constexpr int kBH   = kB / kGY;   // 32
constexpr int kCB   = 8;
constexpr int kNCH  = kBH / kCB;  // 4

// SMEM (floats)
constexpr int kUSd  = kBH;                      // 32
constexpr int kUSnl = kD * kUSd + 4;            // 260
constexpr int kOffV = kNL * kUSnl;              // 1040
constexpr int kVSo  = 36;                       // per-o: 16 e x 2 lanes, pad 4 (bank shift)
constexpr int kVSbp = kO * kVSo + 4;            // 364
constexpr int kOffL = kOffV + (kBH / 2) * kVSbp;   // 1040 + 5824 = 6864
constexpr int kLSbp = 20;
constexpr int kLSnl = (kBH / 2) * kLSbp + 4;       // 324 (mod 32 == 4)
constexpr int kSmemFloats1 = kOffL + kNL * kLSnl;  // 8160
constexpr int kSmemBytes1  = kSmemFloats1 * 4;     // 32640 (x4 CTA = 130KB)
constexpr int kSmemBytes0  = kOffV * 4;            // 4160

typedef unsigned long long u64;

__device__ float g_part[(size_t)kGX * kB * kOE];  // 47.2 MB
__device__ float g_vsum[kB * kOE];

#define FMA2(d, a, b_) asm("fma.rn.f32x2 %0, %1, %2, %0;" : "+l"(d) : "l"(a), "l"(b_))
#define MUL2(d, a, b_) asm("mul.rn.f32x2 %0, %1, %2;" : "=l"(d) : "l"(a), "l"(b_))
#define ADD2(d, a, b_) asm("add.rn.f32x2 %0, %1, %2;" : "=l"(d) : "l"(a), "l"(b_))
#define PACK2(d, lo, hi) \
  asm("mov.b64 %0, {%1, %2};" : "=l"(d) : "r"(__float_as_uint(lo)), "r"(__float_as_uint(hi)))
#define UNPK2(lo, hi, v)                                                \
  do {                                                                  \
    unsigned _l, _h;                                                    \
    asm("mov.b64 {%0, %1}, %2;" : "=r"(_l), "=r"(_h) : "l"(v));         \
    lo = __uint_as_float(_l); hi = __uint_as_float(_h);                 \
  } while (0)

__global__ void noop_kernel() {}

// 4x4 u_ji tile (bias included) for one chunk of 8 batches.
__device__ __forceinline__ void compute_acc(
    u64 acc[4][4], const float* __restrict__ up, const float w[kD][4], u64 bp)
{
#pragma unroll
  for (int k = 0; k < 4; k++)
#pragma unroll
    for (int j = 0; j < 4; j++) acc[k][j] = bp;
#pragma unroll
  for (int d = 0; d < kD; d++) {
    ulonglong2 ua = *(const ulonglong2*)(up + d * kUSd);      // b (0,1),(2,3)
    ulonglong2 ub = *(const ulonglong2*)(up + d * kUSd + 4);  // b (4,5),(6,7)
    u64 w2[4];
    PACK2(w2[0], w[d][0], w[d][0]); PACK2(w2[1], w[d][1], w[d][1]);
    PACK2(w2[2], w[d][2], w[d][2]); PACK2(w2[3], w[d][3], w[d][3]);
    FMA2(acc[0][0], ua.x, w2[0]); FMA2(acc[0][1], ua.x, w2[1]);
    FMA2(acc[0][2], ua.x, w2[2]); FMA2(acc[0][3], ua.x, w2[3]);
    FMA2(acc[1][0], ua.y, w2[0]); FMA2(acc[1][1], ua.y, w2[1]);
    FMA2(acc[1][2], ua.y, w2[2]); FMA2(acc[1][3], ua.y, w2[3]);
    FMA2(acc[2][0], ub.x, w2[0]); FMA2(acc[2][1], ub.x, w2[1]);
    FMA2(acc[2][2], ub.x, w2[2]); FMA2(acc[2][3], ub.x, w2[3]);
    FMA2(acc[3][0], ub.y, w2[0]); FMA2(acc[3][1], ub.y, w2[1]);
    FMA2(acc[3][2], ub.y, w2[2]); FMA2(acc[3][3], ub.y, w2[3]);
  }
}

// MODE 0: c uniform (0.1 folded into squash).  MODE 1: c = softmax_o(<u_ji, g_vsum>).
// acc computed once per chunk, reused across the softmax barriers.
template <int MODE>
__global__ void __launch_bounds__(kTH, 4) pass_kernel(
    const float* __restrict__ u_i,
    const float* __restrict__ W,
    const float* __restrict__ bias)
{
  extern __shared__ float sm[];
  float* u_s = sm;              // [nl(260)][d(32)][b]
  float* v_s = sm + kOffV;      // [b-pair(364)][o(36)][e*2 + (b&1)]
  float* l_s = sm + kOffL;      // [nl(324)][b-pair(20)][o*2] logits -> c

  const int tid = threadIdx.x;
  const int nl  = tid & 3;
  const int eg  = (tid >> 2) & 3;
  const int o   = tid >> 4;
  const int n0  = blockIdx.x * kNL;
  const int bb0 = blockIdx.y * kBH;

  // ---- W slice + bias ----
  float w[kD][4];
  {
    const float* Wp = W + ((size_t)(n0 + nl) * kO + o) * (kD * kE) + eg * 4;
#pragma unroll
    for (int d = 0; d < kD; d++) {
      float4 w4 = *(const float4*)(Wp + d * kE);
      w[d][0] = w4.x; w[d][1] = w4.y; w[d][2] = w4.z; w[d][3] = w4.w;
    }
  }
  const float bv = bias[(n0 + nl) * kO + o];
  u64 bp; PACK2(bp, bv, bv);

  // ---- stage u: [b][n][d] -> [nl][d][b_local] ----
  for (int i = tid; i < kBH * kNL * 2; i += kTH) {  // 256
    int b = i >> 3, nl2 = (i >> 1) & 3, h = i & 1;
    float4 t = *(const float4*)(u_i + ((size_t)(bb0 + b) * kN + n0 + nl2) * kD + h * 4);
    float* du = u_s + nl2 * kUSnl + h * 4 * kUSd + b;
    du[0] = t.x; du[kUSd] = t.y; du[2 * kUSd] = t.z; du[3 * kUSd] = t.w;
  }
  // ---- stage v pair-packed (MODE 1) ----
  if (MODE) {
    for (int i = tid; i < kBH * (kOE / 4); i += kTH) {  // 1280
      int b = i / 40, q = i - b * 40;
      int oo = q >> 2, e0 = (q & 3) * 4;
      float4 t = *(const float4*)(g_vsum + (size_t)(bb0 + b) * kOE + oo * kE + e0);
      float* dv = v_s + (b >> 1) * kVSbp + oo * kVSo + e0 * 2 + (b & 1);
      dv[0] = t.x; dv[2] = t.y; dv[4] = t.z; dv[6] = t.w;
    }
  }
  __syncthreads();

  const float* up_base = u_s + nl * kUSnl;

  for (int ch = 0; ch < kNCH; ch++) {
    const int bc  = ch * kCB;
    const int bc2 = ch * 4;  // b-pair base
    const int bca = bb0 + bc;

    // ---- u_ji tile, computed once, held across barriers ----
    u64 acc[4][4];
    compute_acc(acc, up_base + bc, w, bp);

    if (MODE) {
      // agreement logits (v pair-packed from smem)
      u64 ag[4] = {0ull, 0ull, 0ull, 0ull};
#pragma unroll
      for (int k = 0; k < 4; k++) {
        const float* vp = v_s + (bc2 + k) * kVSbp + o * kVSo + eg * 8;
        ulonglong2 va = *(const ulonglong2*)vp;
        ulonglong2 vb = *(const ulonglong2*)(vp + 4);
        FMA2(ag[k], acc[k][0], va.x);
        FMA2(ag[k], acc[k][1], va.y);
        FMA2(ag[k], acc[k][2], vb.x);
        FMA2(ag[k], acc[k][3], vb.y);
      }
      // eg-reduction (lane bits 2,3), packed u64
#pragma unroll
      for (int k = 0; k < 4; k++) {
        u64 r = __shfl_xor_sync(0xffffffffu, ag[k], 4);
        ADD2(ag[k], ag[k], r);
        r = __shfl_xor_sync(0xffffffffu, ag[k], 8);
        ADD2(ag[k], ag[k], r);
      }
      if (eg == 0) {
        float* ar = l_s + nl * kLSnl + bc2 * kLSbp + o * 2;
#pragma unroll
        for (int k = 0; k < 4; k++)
          *(u64*)(ar + k * kLSbp) = ag[k];
      }
      __syncthreads();

      // pair-softmax for THIS chunk's 16 pair-rows (threads 0-15)
      if (tid < 16) {
        float* row = l_s + (tid >> 2) * kLSnl + (bc2 + (tid & 3)) * kLSbp;
        float ax[kO], ay[kO];
        float sx = 0.f, sy = 0.f;
#pragma unroll
        for (int q = 0; q < kO; q++) {
          float2 t = *(const float2*)(row + q * 2);
          ax[q] = __expf(t.x); ay[q] = __expf(t.y);
          sx += ax[q]; sy += ay[q];
        }
        float ix = 1.f / sx, iy = 1.f / sy;
#pragma unroll
        for (int q = 0; q < kO; q++)
          *(float2*)(row + q * 2) = make_float2(ax[q] * ix, ay[q] * iy);
      }
      __syncthreads();
    }

    // ---- weight by c (acc reused) ----
    u64 v16[16];
    if (MODE) {
      const float* cp = l_s + nl * kLSnl + bc2 * kLSbp + o * 2;
#pragma unroll
      for (int k = 0; k < 4; k++) {
        u64 c2 = *(const u64*)(cp + k * kLSbp);
#pragma unroll
        for (int j = 0; j < 4; j++) MUL2(v16[k * 4 + j], acc[k][j], c2);
      }
    } else {
#pragma unroll
      for (int k = 0; k < 4; k++)
#pragma unroll
        for (int j = 0; j < 4; j++) v16[k * 4 + j] = acc[k][j];
    }

    // reduce-scatter over nl (lane bits 0,1): 2 levels
    u64 v8[8];
    {
      const bool sel = (nl >> 1) & 1;
#pragma unroll
      for (int i = 0; i < 8; i++) {
        u64 send = sel ? v16[i] : v16[8 + i];
        u64 recv = __shfl_xor_sync(0xffffffffu, send, 2);
        u64 keep = sel ? v16[8 + i] : v16[i];
        ADD2(v8[i], keep, recv);
      }
    }
    u64 v4[4];
    {
      const bool sel = nl & 1;
#pragma unroll
      for (int i = 0; i < 4; i++) {
        u64 send = sel ? v8[i] : v8[4 + i];
        u64 recv = __shfl_xor_sync(0xffffffffu, send, 1);
        u64 keep = sel ? v8[4 + i] : v8[i];
        ADD2(v4[i], keep, recv);
      }
    }

    // lane holds batch-pair k = nl, all 4 e-offsets (lo = batch 2k, hi = 2k+1)
    {
      float l0, h0, l1, h1, l2, h2, l3, h3;
      UNPK2(l0, h0, v4[0]); UNPK2(l1, h1, v4[1]);
      UNPK2(l2, h2, v4[2]); UNPK2(l3, h3, v4[3]);
      float* dp = &g_part[((size_t)blockIdx.x * kB + bca + 2 * nl) * kOE
                          + o * kE + eg * 4];
      *(float4*)dp         = make_float4(l0, l1, l2, l3);
      *(float4*)(dp + kOE) = make_float4(h0, h1, h2, h3);
    }
  }
}

// Reduce 288 partials (p-loop split 4-way over lanes) + squash.
__global__ void squash_kernel(float* __restrict__ out, int mode, float scale) {
  int gt = blockIdx.x * blockDim.x + threadIdx.x;
  if (gt >= kB * kO * 4 * 4) return;            // 40960
  int h = gt & 3, eq = (gt >> 2) & 3, row = gt >> 4;  // row = b*10 + o
  const float* pp = g_part + (size_t)row * kE + eq * 4
                  + (size_t)(h * 72) * kB * kOE;
  float4 a = {0.f, 0.f, 0.f, 0.f};
#pragma unroll 4
  for (int p = 0; p < 72; p++) {
    float4 t = *(const float4*)(pp + (size_t)p * kB * kOE);
    a.x += t.x; a.y += t.y; a.z += t.z; a.w += t.w;
  }
  // combine p-quarters (lane bits 0,1)
  a.x += __shfl_xor_sync(0xffffffffu, a.x, 1);
  a.y += __shfl_xor_sync(0xffffffffu, a.y, 1);
  a.z += __shfl_xor_sync(0xffffffffu, a.z, 1);
  a.w += __shfl_xor_sync(0xffffffffu, a.w, 1);
  a.x += __shfl_xor_sync(0xffffffffu, a.x, 2);
  a.y += __shfl_xor_sync(0xffffffffu, a.y, 2);
  a.z += __shfl_xor_sync(0xffffffffu, a.z, 2);
  a.w += __shfl_xor_sync(0xffffffffu, a.w, 2);
  a.x *= scale; a.y *= scale; a.z *= scale; a.w *= scale;
  float n2 = a.x * a.x + a.y * a.y + a.z * a.z + a.w * a.w;
  n2 += __shfl_xor_sync(0xffffffffu, n2, 4);
  n2 += __shfl_xor_sync(0xffffffffu, n2, 8);
  float f = sqrtf(n2) / (1.f + n2);
  float4 v = make_float4(a.x * f, a.y * f, a.z * f, a.w * f);
  if (h == 0) {
    if (mode == 2) {
      *(float4*)(out + (size_t)row * kE + eq * 4) = v;
    } else if (mode == 1) {
      float4 old = *(const float4*)(g_vsum + (size_t)row * kE + eq * 4);
      v.x += old.x; v.y += old.y; v.z += old.z; v.w += old.w;
      *(float4*)(g_vsum + (size_t)row * kE + eq * 4) = v;
    } else {
      *(float4*)(g_vsum + (size_t)row * kE + eq * 4) = v;
    }
  }
}

extern "C" void kernel_launch(void* const* d_in, const int* in_sizes, int n_in,
                              void* d_out, int out_size) {
  const float* u    = (const float*)d_in[0];
  const float* W    = (const float*)d_in[1];
  const float* bias = (const float*)d_in[2];
  float* out = (float*)d_out;

  cudaFuncSetAttribute((const void*)pass_kernel<0>,
                       cudaFuncAttributeMaxDynamicSharedMemorySize, kSmemBytes0);
  cudaFuncSetAttribute((const void*)pass_kernel<1>,
                       cudaFuncAttributeMaxDynamicSharedMemorySize, kSmemBytes1);

  dim3 grid(kGX, kGY);  // 2304 blocks, 4 CTAs/SM

  noop_kernel<<<1, 32>>>();  // keeps ncu -s 5 -c 1 on the 2nd pass_kernel<1>

  pass_kernel<0><<<grid, kTH, kSmemBytes0>>>(u, W, bias);
  squash_kernel<<<160, 256>>>(nullptr, 0, 0.1f);

  pass_kernel<1><<<grid, kTH, kSmemBytes1>>>(u, W, bias);
  squash_kernel<<<160, 256>>>(nullptr, 1, 1.0f);

  pass_kernel<1><<<grid, kTH, kSmemBytes1>>>(u, W, bias);
  squash_kernel<<<160, 256>>>(out, 2, 1.0f);
}

// round 14
// speedup vs baseline: 1.2843x; 1.2843x over previous
#include <cuda_runtime.h>
#include <math.h>

// Problem constants
constexpr int kB = 256, kN = 1152, kD = 8, kO = 10, kE = 16;
constexpr int kOE = kO * kE;  // 160

// Persistent fused kernel: 288 blocks (144 n-groups x 2 batch halves),
// 320 threads, 2 CTAs/SM -> all blocks co-resident (288 <= 296).
constexpr int kNL   = 8;
constexpr int kTH   = 320;        // tid = nl(b0-2) + eg(b3-4) + o(b5+)
constexpr int kNG   = kN / kNL;   // 144 n-groups
constexpr int kGrid = kNG * 2;    // 288
constexpr int kBH   = kB / 2;     // 128 batches per block
constexpr int kCB   = 8;
constexpr int kNCH  = kBH / kCB;  // 16 chunks

// SMEM (floats)
constexpr int kUSd  = kBH;                    // 128
constexpr int kUSnl = kD * kUSd + 4;          // 1028
constexpr int kOffL = kNL * kUSnl;            // 8224
constexpr int kLSbp = 20;
constexpr int kLSnl = (kBH / 2) * kLSbp + 4;  // 1284 (mod 32 == 4)
constexpr int kSmemFloats = kOffL + kNL * kLSnl;  // 18496
constexpr int kSmemBytes  = kSmemFloats * 4;      // 73984 (x2 CTA = 148KB)

typedef unsigned long long u64;

__device__ float g_part[(size_t)kNG * kB * kOE];  // 23.6 MB
__device__ float g_vsum[kB * kOE];
__device__ unsigned g_bar;  // monotonic ticket barrier (never reset)

#define FMA2(d, a, b_) asm("fma.rn.f32x2 %0, %1, %2, %0;" : "+l"(d) : "l"(a), "l"(b_))
#define MUL2(d, a, b_) asm("mul.rn.f32x2 %0, %1, %2;" : "=l"(d) : "l"(a), "l"(b_))
#define ADD2(d, a, b_) asm("add.rn.f32x2 %0, %1, %2;" : "=l"(d) : "l"(a), "l"(b_))
#define PACK2(d, lo, hi) \
  asm("mov.b64 %0, {%1, %2};" : "=l"(d) : "r"(__float_as_uint(lo)), "r"(__float_as_uint(hi)))
#define UNPK2(lo, hi, v)                                                \
  do {                                                                  \
    unsigned _l, _h;                                                    \
    asm("mov.b64 {%0, %1}, %2;" : "=r"(_l), "=r"(_h) : "l"(v));         \
    lo = __uint_as_float(_l); hi = __uint_as_float(_h);                 \
  } while (0)

// Grid-wide barrier: ticket-based, monotonic counter (graph-replay safe).
__device__ __forceinline__ void grid_barrier(int tid) {
  __syncthreads();
  if (tid == 0) {
    __threadfence();
    unsigned t = atomicAdd(&g_bar, 1u);
    unsigned target = (t / (unsigned)kGrid + 1u) * (unsigned)kGrid;
    while (*(volatile unsigned*)&g_bar < target) __nanosleep(64);
  }
  __syncthreads();
}

// 4x4 u_ji tile (bias included) for one chunk of 8 batches.
__device__ __forceinline__ void compute_acc(
    u64 acc[4][4], const float* __restrict__ up, const float w[kD][4], u64 bp)
{
#pragma unroll
  for (int k = 0; k < 4; k++)
#pragma unroll
    for (int j = 0; j < 4; j++) acc[k][j] = bp;
#pragma unroll
  for (int d = 0; d < kD; d++) {
    ulonglong2 ua = *(const ulonglong2*)(up + d * kUSd);      // b (0,1),(2,3)
    ulonglong2 ub = *(const ulonglong2*)(up + d * kUSd + 4);  // b (4,5),(6,7)
    u64 w2[4];
    PACK2(w2[0], w[d][0], w[d][0]); PACK2(w2[1], w[d][1], w[d][1]);
    PACK2(w2[2], w[d][2], w[d][2]); PACK2(w2[3], w[d][3], w[d][3]);
    FMA2(acc[0][0], ua.x, w2[0]); FMA2(acc[0][1], ua.x, w2[1]);
    FMA2(acc[0][2], ua.x, w2[2]); FMA2(acc[0][3], ua.x, w2[3]);
    FMA2(acc[1][0], ua.y, w2[0]); FMA2(acc[1][1], ua.y, w2[1]);
    FMA2(acc[1][2], ua.y, w2[2]); FMA2(acc[1][3], ua.y, w2[3]);
    FMA2(acc[2][0], ub.x, w2[0]); FMA2(acc[2][1], ub.x, w2[1]);
    FMA2(acc[2][2], ub.x, w2[2]); FMA2(acc[2][3], ub.x, w2[3]);
    FMA2(acc[3][0], ub.y, w2[0]); FMA2(acc[3][1], ub.y, w2[1]);
    FMA2(acc[3][2], ub.y, w2[2]); FMA2(acc[3][3], ub.y, w2[3]);
  }
}

// One routing pass over this block's 128 batches. acc held across barriers.
// MODE 0: c uniform (0.1 folded into squash).  MODE 1: c = softmax_o(<u_ji, v>).
template <int MODE>
__device__ __forceinline__ void pass_phase(
    float* u_s, float* l_s, int tid, int nl, int eg, int o,
    int bb0, int ng, const float w[kD][4], u64 bp)
{
  const float* up_base = u_s + nl * kUSnl;
  const int mm = ((nl >> 2) & 1) * 8 + ((nl >> 1) & 1) * 4 + (nl & 1) * 2;
  const int kk = mm >> 2, j0 = mm & 3;

  for (int ch = 0; ch < kNCH; ch++) {
    const int bc  = ch * kCB;
    const int bc2 = ch * 4;
    const int bca = bb0 + bc;

    // prefetch v (L1-bypassed: g_vsum is rewritten in-kernel)
    float4 vA[4], vB[4];
    if (MODE) {
#pragma unroll
      for (int k = 0; k < 4; k++) {
        const float* vp0 = g_vsum + (size_t)(bca + 2 * k) * kOE + o * kE + eg * 4;
        vA[k] = __ldcg((const float4*)vp0);
        vB[k] = __ldcg((const float4*)(vp0 + kOE));
      }
    }

    u64 acc[4][4];
    compute_acc(acc, up_base + bc, w, bp);

    if (MODE) {
      u64 ag[4] = {0ull, 0ull, 0ull, 0ull};
#pragma unroll
      for (int k = 0; k < 4; k++) {
        u64 vp;
        PACK2(vp, vA[k].x, vB[k].x); FMA2(ag[k], acc[k][0], vp);
        PACK2(vp, vA[k].y, vB[k].y); FMA2(ag[k], acc[k][1], vp);
        PACK2(vp, vA[k].z, vB[k].z); FMA2(ag[k], acc[k][2], vp);
        PACK2(vp, vA[k].w, vB[k].w); FMA2(ag[k], acc[k][3], vp);
      }
      // eg-reduction (lane bits 3,4), packed u64
#pragma unroll
      for (int k = 0; k < 4; k++) {
        u64 r = __shfl_xor_sync(0xffffffffu, ag[k], 8);
        ADD2(ag[k], ag[k], r);
        r = __shfl_xor_sync(0xffffffffu, ag[k], 16);
        ADD2(ag[k], ag[k], r);
      }
      if (eg == 0) {
        float* ar = l_s + nl * kLSnl + bc2 * kLSbp + o * 2;
#pragma unroll
        for (int k = 0; k < 4; k++)
          *(u64*)(ar + k * kLSbp) = ag[k];
      }
      __syncthreads();

      // pair-softmax for this chunk's 32 pair-rows
      if (tid < 32) {
        float* row = l_s + (tid >> 2) * kLSnl + (bc2 + (tid & 3)) * kLSbp;
        float ax[kO], ay[kO];
        float sx = 0.f, sy = 0.f;
#pragma unroll
        for (int q = 0; q < kO; q++) {
          float2 t = *(const float2*)(row + q * 2);
          ax[q] = __expf(t.x); ay[q] = __expf(t.y);
          sx += ax[q]; sy += ay[q];
        }
        float ix = 1.f / sx, iy = 1.f / sy;
#pragma unroll
        for (int q = 0; q < kO; q++)
          *(float2*)(row + q * 2) = make_float2(ax[q] * ix, ay[q] * iy);
      }
      __syncthreads();
    }

    // weight by c (acc reused)
    u64 v16[16];
    if (MODE) {
      const float* cp = l_s + nl * kLSnl + bc2 * kLSbp + o * 2;
#pragma unroll
      for (int k = 0; k < 4; k++) {
        u64 c2 = *(const u64*)(cp + k * kLSbp);
#pragma unroll
        for (int j = 0; j < 4; j++) MUL2(v16[k * 4 + j], acc[k][j], c2);
      }
    } else {
#pragma unroll
      for (int k = 0; k < 4; k++)
#pragma unroll
        for (int j = 0; j < 4; j++) v16[k * 4 + j] = acc[k][j];
    }

    // reduce-scatter over nl (lane bits 0-2): 3 levels
    u64 v8[8];
    {
      const bool sel = (nl >> 2) & 1;
#pragma unroll
      for (int i = 0; i < 8; i++) {
        u64 send = sel ? v16[i] : v16[8 + i];
        u64 recv = __shfl_xor_sync(0xffffffffu, send, 4);
        u64 keep = sel ? v16[8 + i] : v16[i];
        ADD2(v8[i], keep, recv);
      }
    }
    u64 v4[4];
    {
      const bool sel = (nl >> 1) & 1;
#pragma unroll
      for (int i = 0; i < 4; i++) {
        u64 send = sel ? v8[i] : v8[4 + i];
        u64 recv = __shfl_xor_sync(0xffffffffu, send, 2);
        u64 keep = sel ? v8[4 + i] : v8[i];
        ADD2(v4[i], keep, recv);
      }
    }
    u64 v2[2];
    {
      const bool sel = nl & 1;
#pragma unroll
      for (int i = 0; i < 2; i++) {
        u64 send = sel ? v4[i] : v4[2 + i];
        u64 recv = __shfl_xor_sync(0xffffffffu, send, 1);
        u64 keep = sel ? v4[2 + i] : v4[i];
        ADD2(v2[i], keep, recv);
      }
    }
    {
      float l0, h0, l1, h1;
      UNPK2(l0, h0, v2[0]); UNPK2(l1, h1, v2[1]);
      float* dp = &g_part[((size_t)ng * kB + bca + 2 * kk) * kOE
                          + o * kE + eg * 4 + j0];
      *(float2*)dp         = make_float2(l0, l1);
      *(float2*)(dp + kOE) = make_float2(h0, h1);
    }
  }
}

// Reduce 144 partials + squash. 40960 items = blocks 0..127 exactly
// (warp-uniform activity; shfl masks safe).
__device__ __forceinline__ void squash_phase(float* __restrict__ out,
                                             int mode, float scale, int tid) {
  if (blockIdx.x >= 128) return;
  int gt = blockIdx.x * kTH + tid;
  int h = gt & 3, eq = (gt >> 2) & 3, row = gt >> 4;  // row = b*10 + o
  const float* pp = g_part + (size_t)row * kE + eq * 4
                  + (size_t)(h * 36) * kB * kOE;
  float4 a = {0.f, 0.f, 0.f, 0.f};
#pragma unroll 4
  for (int p = 0; p < 36; p++) {
    float4 t = __ldcg((const float4*)(pp + (size_t)p * kB * kOE));
    a.x += t.x; a.y += t.y; a.z += t.z; a.w += t.w;
  }
  a.x += __shfl_xor_sync(0xffffffffu, a.x, 1);
  a.y += __shfl_xor_sync(0xffffffffu, a.y, 1);
  a.z += __shfl_xor_sync(0xffffffffu, a.z, 1);
  a.w += __shfl_xor_sync(0xffffffffu, a.w, 1);
  a.x += __shfl_xor_sync(0xffffffffu, a.x, 2);
  a.y += __shfl_xor_sync(0xffffffffu, a.y, 2);
  a.z += __shfl_xor_sync(0xffffffffu, a.z, 2);
  a.w += __shfl_xor_sync(0xffffffffu, a.w, 2);
  a.x *= scale; a.y *= scale; a.z *= scale; a.w *= scale;
  float n2 = a.x * a.x + a.y * a.y + a.z * a.z + a.w * a.w;
  n2 += __shfl_xor_sync(0xffffffffu, n2, 4);
  n2 += __shfl_xor_sync(0xffffffffu, n2, 8);
  float f = sqrtf(n2) / (1.f + n2);
  float4 v = make_float4(a.x * f, a.y * f, a.z * f, a.w * f);
  if (h == 0) {
    if (mode == 2) {
      *(float4*)(out + (size_t)row * kE + eq * 4) = v;
    } else if (mode == 1) {
      float4 old = *(const float4*)(g_vsum + (size_t)row * kE + eq * 4);
      v.x += old.x; v.y += old.y; v.z += old.z; v.w += old.w;
      *(float4*)(g_vsum + (size_t)row * kE + eq * 4) = v;
    } else {
      *(float4*)(g_vsum + (size_t)row * kE + eq * 4) = v;
    }
  }
}

__global__ void __launch_bounds__(kTH, 2) fused_kernel(
    const float* __restrict__ u_i,
    const float* __restrict__ W,
    const float* __restrict__ bias,
    float* __restrict__ out)
{
  extern __shared__ float sm[];
  float* u_s = sm;            // [nl(1028)][d(128)][b]
  float* l_s = sm + kOffL;    // [nl(1284)][b-pair(20)][o*2]

  const int tid = threadIdx.x;
  const int nl  = tid & 7;
  const int eg  = (tid >> 3) & 3;
  const int o   = tid >> 5;
  const int ng  = blockIdx.x >> 1;
  const int n0  = ng * kNL;
  const int bb0 = (blockIdx.x & 1) * kBH;

  // W slice + bias, once for all 3 iterations
  float w[kD][4];
  {
    const float* Wp = W + ((size_t)(n0 + nl) * kO + o) * (kD * kE) + eg * 4;
#pragma unroll
    for (int d = 0; d < kD; d++) {
      float4 w4 = *(const float4*)(Wp + d * kE);
      w[d][0] = w4.x; w[d][1] = w4.y; w[d][2] = w4.z; w[d][3] = w4.w;
    }
  }
  const float bv = bias[(n0 + nl) * kO + o];
  u64 bp; PACK2(bp, bv, bv);

  // stage u once for all 3 iterations: [b][n][d] -> [nl][d][b_local]
  for (int i = tid; i < kBH * kNL * 2; i += kTH) {
    int b = i >> 4, nl2 = (i >> 1) & 7, h = i & 1;
    float4 t = *(const float4*)(u_i + ((size_t)(bb0 + b) * kN + n0 + nl2) * kD + h * 4);
    float* du = u_s + nl2 * kUSnl + h * 4 * kUSd + b;
    du[0] = t.x; du[kUSd] = t.y; du[2 * kUSd] = t.z; du[3 * kUSd] = t.w;
  }
  __syncthreads();

  // iteration 1: uniform c (0.1 folded into squash scale)
  pass_phase<0>(u_s, l_s, tid, nl, eg, o, bb0, ng, w, bp);
  grid_barrier(tid);
  squash_phase(out, 0, 0.1f, tid);   // g_vsum = v1
  grid_barrier(tid);

  // iteration 2
  pass_phase<1>(u_s, l_s, tid, nl, eg, o, bb0, ng, w, bp);
  grid_barrier(tid);
  squash_phase(out, 1, 1.0f, tid);   // g_vsum = v1 + v2
  grid_barrier(tid);

  // iteration 3
  pass_phase<1>(u_s, l_s, tid, nl, eg, o, bb0, ng, w, bp);
  grid_barrier(tid);
  squash_phase(out, 2, 1.0f, tid);   // out = v3
}

extern "C" void kernel_launch(void* const* d_in, const int* in_sizes, int n_in,
                              void* d_out, int out_size) {
  const float* u    = (const float*)d_in[0];
  const float* W    = (const float*)d_in[1];
  const float* bias = (const float*)d_in[2];
  float* out = (float*)d_out;

  cudaFuncSetAttribute((const void*)fused_kernel,
                       cudaFuncAttributeMaxDynamicSharedMemorySize, kSmemBytes);

  fused_kernel<<<kGrid, kTH, kSmemBytes>>>(u, W, bias, out);
}